// round 14
// baseline (speedup 1.0000x reference)
#include <cuda_runtime.h>
#include <cuda_bf16.h>
#include <math.h>

#define NC    128
#define LL    250
#define MM    32
#define NCOL  250000
#define TOT   32000000
#define PERB  8000000

// Scratch
__device__ float g_buf0[32000000];  // u (packed) -> G (glu out, flat) -> u_inter
__device__ float g_buf1[32000000];  // yT -> Lf (lw out, flat)
__device__ float g_kern[NC * LL];
__device__ double g_stats[8];
__device__ float g_mu[4], g_inv[4];
__device__ unsigned g_owAhi[256 * 64];  // ow bf16 hi (u32-packed pairs)
__device__ unsigned g_owAlo[256 * 64];  // ow bf16 lo
__device__ unsigned g_lwWhi[128 * 64];  // lw bf16 hi
__device__ unsigned g_lwWlo[128 * 64];  // lw bf16 lo
__device__ unsigned g_uhi[16384000];    // u bf16 hi: [row=bb*128+h][128 u32]
__device__ unsigned g_ulo[16384000];    // u bf16 lo

// ---------------------------------------------------------------------------
__device__ __forceinline__ void mma16816(float& c0, float& c1, float& c2, float& c3,
                                         unsigned a0, unsigned a1, unsigned a2, unsigned a3,
                                         unsigned b0, unsigned b1) {
    asm volatile(
        "mma.sync.aligned.m16n8k16.row.col.f32.bf16.bf16.f32 "
        "{%0,%1,%2,%3}, {%4,%5,%6,%7}, {%8,%9}, {%0,%1,%2,%3};"
        : "+f"(c0), "+f"(c1), "+f"(c2), "+f"(c3)
        : "r"(a0), "r"(a1), "r"(a2), "r"(a3), "r"(b0), "r"(b1));
}
__device__ __forceinline__ void ldm4(unsigned& r0, unsigned& r1, unsigned& r2, unsigned& r3,
                                     unsigned a) {
    asm volatile("ldmatrix.sync.aligned.m8n8.x4.shared.b16 {%0,%1,%2,%3}, [%4];"
        : "=r"(r0), "=r"(r1), "=r"(r2), "=r"(r3) : "r"(a));
}
__device__ __forceinline__ unsigned pkbf(__nv_bfloat16 a, __nv_bfloat16 b) {
    unsigned r;
    asm("mov.b32 %0, {%1, %2};" : "=r"(r)
        : "h"(*(unsigned short*)&a), "h"(*(unsigned short*)&b));
    return r;
}
__device__ __forceinline__ unsigned smem_u32p(const void* p) {
    return (unsigned)__cvta_generic_to_shared(p);
}

// ---------------------------------------------------------------------------
__global__ void pack_intra(const float* __restrict__ x) {
    __shared__ float tile[32][33];
    int bh = blockIdx.y;
    int b = bh >> 7, h = bh & 127;
    int tk = blockIdx.x & 7;
    int ts = blockIdx.x >> 3;
    int k = tk * 32 + threadIdx.y;
    int s = ts * 32 + threadIdx.x;
    if (k < 250 && s < 250)
        tile[threadIdx.y][threadIdx.x] = x[(((long)bh * 250 + k) * 250) + s];
    __syncthreads();
    int s2 = ts * 32 + threadIdx.y;
    int k2 = tk * 32 + threadIdx.x;
    if (s2 < 250 && k2 < 250)
        g_buf0[(((long)(b * 250 + s2) * 128 + h) * 250) + k2] = tile[threadIdx.x][threadIdx.y];
}

// ---------------------------------------------------------------------------
__global__ void kern_compute(const float* __restrict__ log_dt,
                             const float* __restrict__ logA_re,
                             const float* __restrict__ A_im,
                             const float* __restrict__ C_re,
                             const float* __restrict__ C_im) {
    __shared__ float sCr[MM], sCi[MM], sar[MM], sai[MM];
    int h = blockIdx.x;
    int t = threadIdx.x;
    if (t < MM) {
        float dt  = expf(log_dt[h]);
        float Are = -expf(logA_re[h * MM + t]);
        float Aim = A_im[h * MM + t];
        float ar = dt * Are, ai = dt * Aim;
        float ea = expf(ar);
        float sb, cb; sincosf(ai, &sb, &cb);
        float er = ea * cb - 1.f, ei = ea * sb;
        float den = Are * Are + Aim * Aim;
        float qr = (er * Are + ei * Aim) / den;
        float qi = (ei * Are - er * Aim) / den;
        float cr = C_re[h * MM + t], ci = C_im[h * MM + t];
        sCr[t] = cr * qr - ci * qi;
        sCi[t] = cr * qi + ci * qr;
        sar[t] = ar; sai[t] = ai;
    }
    __syncthreads();
    if (t < LL) {
        float fl = (float)t;
        float sum = 0.f;
        #pragma unroll
        for (int m = 0; m < MM; ++m) {
            float ea = expf(sar[m] * fl);
            float sb, cb; sincosf(sai[m] * fl, &sb, &cb);
            sum += ea * (sCr[m] * cb - sCi[m] * sb);
        }
        g_kern[h * LL + t] = 2.f * sum;
    }
}

// ---------------------------------------------------------------------------
// Pre-convert u (g_buf0 flat rows of 250) to bf16 hi/lo pair-packed planes.
__global__ void conv_u_bf16() {
    long i = (long)blockIdx.x * 256 + threadIdx.x;   // 16,384,000
    int kp = (int)(i & 127);
    long row = i >> 7;
    float2 v = make_float2(0.f, 0.f);
    if (kp < 125) v = *(const float2*)&g_buf0[row * 250 + kp * 2];
    __nv_bfloat16 h0 = __float2bfloat16(v.x);
    __nv_bfloat16 h1 = __float2bfloat16(v.y);
    __nv_bfloat16 l0 = __float2bfloat16(v.x - __bfloat162float(h0));
    __nv_bfloat16 l1 = __float2bfloat16(v.y - __bfloat162float(h1));
    g_uhi[i] = pkbf(h0, h1);
    g_ulo[i] = pkbf(l0, l1);
}

// ---------------------------------------------------------------------------
// Conv as per-h Toeplitz GEMM via mma.sync bf16 2-split + D*u + GELU.
// Block: (h, 128 bb-rows, 64 t-cols). colblk c uses K = 64(c+1) true k.
// Dyn smem: Uhi u32[128][132] @0 (67584) | Ulo @67584 (67584)
//           | Bthi u32[64][132] @135168 (33792) | Btlo @168960 (33792)
//           | skphi bf16[512] @202752 (1024) | skplo @203776 (1024) -> 204800
__global__ void __launch_bounds__(256)
conv_mma(const float* __restrict__ D) {
    extern __shared__ char dsm[];
    unsigned* Uhi = (unsigned*)dsm;
    unsigned* Ulo = (unsigned*)(dsm + 67584);
    unsigned* Bthi = (unsigned*)(dsm + 135168);
    unsigned* Btlo = (unsigned*)(dsm + 168960);
    __nv_bfloat16* skphi = (__nv_bfloat16*)(dsm + 202752);
    __nv_bfloat16* skplo = (__nv_bfloat16*)(dsm + 203776);

    int tid = threadIdx.x;
    int w = tid >> 5, lane = tid & 31;
    int g = lane >> 2, tg = lane & 3;
    int mw = w >> 1, nw = w & 1;
    int h = blockIdx.y;
    int rowblk = blockIdx.x >> 2, colblk = blockIdx.x & 3;
    int r0 = rowblk * 128, t0 = colblk * 64;
    int KS = 4 * (colblk + 1);
    int kpmax = 32 * (colblk + 1);

    // padded kernel (hi/lo): skp[256 + k] = kern[k], zeros elsewhere
    for (int i = tid; i < 512; i += 256) {
        float v = (i >= 256 && i < 506) ? g_kern[h * 250 + i - 256] : 0.f;
        __nv_bfloat16 hi = __float2bfloat16(v);
        skphi[i] = hi;
        skplo[i] = __float2bfloat16(v - __bfloat162float(hi));
    }
    // copy U hi/lo planes (pre-converted)
    {
        int q4 = kpmax >> 2;
        int nu4 = 128 * q4;
        for (int i = tid; i < nu4; i += 256) {
            int r = i / q4, q = i - r * q4;
            int bb = r0 + r; if (bb > 999) bb = 999;
            long src = (long)(bb * 128 + h) * 32 + q;
            *(uint4*)&Uhi[r * 132 + q * 4] = ((const uint4*)g_uhi)[src];
            *(uint4*)&Ulo[r * 132 + q * 4] = ((const uint4*)g_ulo)[src];
        }
    }
    __syncthreads();
    // build Toeplitz B hi/lo: Bt[t][kp pair] = kern[t0+t - k], k = 2kp, 2kp+1
    {
        int nb = 64 * kpmax;
        for (int i = tid; i < nb; i += 256) {
            int t = i / kpmax, kp = i - t * kpmax;
            int idx = 256 + t0 + t - 2 * kp;
            Bthi[t * 132 + kp] = pkbf(skphi[idx], skphi[idx - 1]);
            Btlo[t * 132 + kp] = pkbf(skplo[idx], skplo[idx - 1]);
        }
    }
    __syncthreads();

    unsigned aAddr = smem_u32p(Uhi)
        + (((lane & 7) + ((lane >> 3) & 1) * 8 + mw * 32) * 132 + (lane >> 4) * 4) * 4;
    unsigned bAddr = smem_u32p(Bthi)
        + (((lane & 7) + (lane >> 4) * 8 + nw * 32) * 132 + ((lane >> 3) & 1) * 4) * 4;

    float acc[2][4][4];
    #pragma unroll
    for (int i = 0; i < 2; ++i)
        #pragma unroll
        for (int j = 0; j < 4; ++j)
            #pragma unroll
            for (int q = 0; q < 4; ++q) acc[i][j][q] = 0.f;

    #pragma unroll 4
    for (int ks = 0; ks < KS; ++ks) {
        unsigned koff = (unsigned)ks * 32u;
        unsigned bh0[4], bh1[4], bl0[4], bl1[4];
        #pragma unroll
        for (int jp = 0; jp < 2; ++jp) {
            ldm4(bh0[2 * jp], bh1[2 * jp], bh0[2 * jp + 1], bh1[2 * jp + 1],
                 bAddr + jp * 16 * 528 + koff);
            ldm4(bl0[2 * jp], bl1[2 * jp], bl0[2 * jp + 1], bl1[2 * jp + 1],
                 bAddr + 33792 + jp * 16 * 528 + koff);
        }
        #pragma unroll
        for (int i = 0; i < 2; ++i) {
            unsigned ah0, ah1, ah2, ah3, al0, al1, al2, al3;
            ldm4(ah0, ah1, ah2, ah3, aAddr + i * 16 * 528 + koff);
            ldm4(al0, al1, al2, al3, aAddr + 67584 + i * 16 * 528 + koff);
            #pragma unroll
            for (int j = 0; j < 4; ++j) {
                mma16816(acc[i][j][0], acc[i][j][1], acc[i][j][2], acc[i][j][3],
                         ah0, ah1, ah2, ah3, bh0[j], bh1[j]);
                mma16816(acc[i][j][0], acc[i][j][1], acc[i][j][2], acc[i][j][3],
                         ah0, ah1, ah2, ah3, bl0[j], bl1[j]);
                mma16816(acc[i][j][0], acc[i][j][1], acc[i][j][2], acc[i][j][3],
                         al0, al1, al2, al3, bh0[j], bh1[j]);
            }
        }
    }

    // Epilogue: + D*u (fp32 from g_buf0), gelu, store yT[h][bb*250 + t]
    float dh = D[h];
    #pragma unroll
    for (int i = 0; i < 2; ++i) {
        int ma = mw * 32 + i * 16 + g;
        long bba = r0 + ma, bbb = bba + 8;
        #pragma unroll
        for (int j = 0; j < 4; ++j) {
            int t = t0 + nw * 32 + j * 8 + tg * 2;
            if (t < 250) {
                if (bba < 1000) {
                    float2 uv = *(const float2*)&g_buf0[(bba * 128 + h) * 250 + t];
                    float y0 = acc[i][j][0] + dh * uv.x;
                    float y1 = acc[i][j][1] + dh * uv.y;
                    float e0 = y0 + 0.044715f * y0 * y0 * y0;
                    float e1 = y1 + 0.044715f * y1 * y1 * y1;
                    float2 gv;
                    gv.x = 0.5f * y0 * (1.f + tanhf(0.7978845608f * e0));
                    gv.y = 0.5f * y1 * (1.f + tanhf(0.7978845608f * e1));
                    *(float2*)&g_buf1[(long)h * NCOL + bba * 250 + t] = gv;
                }
                if (bbb < 1000) {
                    float2 uv = *(const float2*)&g_buf0[(bbb * 128 + h) * 250 + t];
                    float y0 = acc[i][j][2] + dh * uv.x;
                    float y1 = acc[i][j][3] + dh * uv.y;
                    float e0 = y0 + 0.044715f * y0 * y0 * y0;
                    float e1 = y1 + 0.044715f * y1 * y1 * y1;
                    float2 gv;
                    gv.x = 0.5f * y0 * (1.f + tanhf(0.7978845608f * e0));
                    gv.y = 0.5f * y1 * (1.f + tanhf(0.7978845608f * e1));
                    *(float2*)&g_buf1[(long)h * NCOL + bbb * 250 + t] = gv;
                }
            }
        }
    }
}

// ---------------------------------------------------------------------------
// Pre-convert weights to bf16 hi/lo planes.
__global__ void conv_ow_bf16(const float* __restrict__ ow) {
    int idx = blockIdx.x * 256 + threadIdx.x;
    int o = idx >> 6, kp = idx & 63;
    float v0 = ow[o * 128 + kp * 2];
    float v1 = ow[o * 128 + kp * 2 + 1];
    __nv_bfloat16 h0 = __float2bfloat16(v0);
    __nv_bfloat16 h1 = __float2bfloat16(v1);
    __nv_bfloat16 l0 = __float2bfloat16(v0 - __bfloat162float(h0));
    __nv_bfloat16 l1 = __float2bfloat16(v1 - __bfloat162float(h1));
    g_owAhi[o * 64 + kp] = pkbf(h0, h1);
    g_owAlo[o * 64 + kp] = pkbf(l0, l1);
}

__global__ void conv_lw_bf16(const float* __restrict__ W) {
    int idx = blockIdx.x * 256 + threadIdx.x;
    int c = idx >> 6, kp = idx & 63;
    float v0 = W[c * 128 + kp * 2];
    float v1 = W[c * 128 + kp * 2 + 1];
    __nv_bfloat16 h0 = __float2bfloat16(v0);
    __nv_bfloat16 h1 = __float2bfloat16(v1);
    __nv_bfloat16 l0 = __float2bfloat16(v0 - __bfloat162float(h0));
    __nv_bfloat16 l1 = __float2bfloat16(v1 - __bfloat162float(h1));
    g_lwWhi[c * 64 + kp] = pkbf(h0, h1);
    g_lwWlo[c * 64 + kp] = pkbf(l0, l1);
}

// ---------------------------------------------------------------------------
// ow GEMM + GLU: fully smem-resident operands, sync-free mainloop (R13).
__global__ void __launch_bounds__(256)
gemm_ow_mma(const float* __restrict__ bias) {
    extern __shared__ char dsm[];
    unsigned* Ahi = (unsigned*)dsm;
    __nv_bfloat16* Bs16 = (__nv_bfloat16*)(dsm + 139264);
    float* sbias = (float*)(dsm + 189440);

    int tid = threadIdx.x;
    int w = tid >> 5, lane = tid & 31;
    int g = lane >> 2, tg = lane & 3;
    int mw = w >> 1, nw = w & 1;
    long n0 = (long)blockIdx.x * 64;

    sbias[tid] = bias[tid];

    #pragma unroll
    for (int p = 0; p < 16; ++p) {
        int i = tid + p * 256;
        int o = i >> 4, q = i & 15;
        uint4 vh = ((const uint4*)g_owAhi)[o * 16 + q];
        uint4 vl = ((const uint4*)g_owAlo)[o * 16 + q];
        *(uint4*)&Ahi[o * 68 + q * 4] = vh;
        *(uint4*)(dsm + 69632 + (o * 68 + q * 4) * 4) = vl;
    }

    for (int i = tid; i < 128 * 64; i += 256) {
        int hk = i >> 6, c = i & 63;
        long col = n0 + c; if (col >= NCOL) col = NCOL - 1;
        float v = g_buf1[(long)hk * NCOL + col];
        __nv_bfloat16 hi = __float2bfloat16(v);
        __nv_bfloat16 lo = __float2bfloat16(v - __bfloat162float(hi));
        __nv_bfloat16* bp = Bs16 + c * 392;
        bp[hk] = hi; bp[hk + 128] = lo; bp[hk + 256] = hi;
    }
    __syncthreads();

    unsigned aAddr = smem_u32p(Ahi)
        + (((lane & 7) + ((lane >> 3) & 1) * 8 + mw * 32) * 68 + (lane >> 4) * 4) * 4;
    unsigned bAddr = smem_u32p(Bs16)
        + ((lane & 7) + (lane >> 4) * 8 + nw * 32) * 784 + ((lane >> 3) & 1) * 16;

    float acc[4][4][4];
    #pragma unroll
    for (int i = 0; i < 4; ++i)
        #pragma unroll
        for (int j = 0; j < 4; ++j)
            #pragma unroll
            for (int q = 0; q < 4; ++q) acc[i][j][q] = 0.f;

    const unsigned tOff[4] = {0u, 16u * 272u, 128u * 272u, 144u * 272u};

    #pragma unroll
    for (int ks = 0; ks < 24; ++ks) {
        unsigned aoff = (ks < 16) ? (unsigned)(ks & 7) * 32u
                                  : 69632u + (unsigned)(ks - 16) * 32u;
        unsigned bf0[4], bf1[4];
        #pragma unroll
        for (int jp = 0; jp < 2; ++jp)
            ldm4(bf0[2 * jp], bf1[2 * jp], bf0[2 * jp + 1], bf1[2 * jp + 1],
                 bAddr + jp * 16 * 784 + ks * 32);
        #pragma unroll
        for (int i = 0; i < 4; ++i) {
            unsigned a0, a1, a2, a3;
            ldm4(a0, a1, a2, a3, aAddr + tOff[i] + aoff);
            #pragma unroll
            for (int j = 0; j < 4; ++j)
                mma16816(acc[i][j][0], acc[i][j][1], acc[i][j][2], acc[i][j][3],
                         a0, a1, a2, a3, bf0[j], bf1[j]);
        }
    }

    #pragma unroll
    for (int i = 0; i < 2; ++i) {
        int oa = mw * 32 + i * 16 + g;
        int ob = oa + 8;
        float b1a = sbias[oa],       b1b = sbias[ob];
        float b2a = sbias[128 + oa], b2b = sbias[128 + ob];
        #pragma unroll
        for (int j = 0; j < 4; ++j) {
            int cl = nw * 32 + j * 8 + tg * 2;
            long col = n0 + cl;
            if (col < NCOL) {
                int bb = (int)(col / 250);
                int l  = (int)(col - (long)bb * 250);
                float z1a = acc[i][j][0] + b1a;
                float z1b = acc[i][j][1] + b1a;
                float z2a = acc[i + 2][j][0] + b2a;
                float z2b = acc[i + 2][j][1] + b2a;
                float2 gv;
                gv.x = z1a / (1.f + expf(-z2a));
                gv.y = z1b / (1.f + expf(-z2b));
                *(float2*)&g_buf0[((long)bb * 128 + oa) * 250 + l] = gv;
                float z3a = acc[i][j][2] + b1b;
                float z3b = acc[i][j][3] + b1b;
                float z4a = acc[i + 2][j][2] + b2b;
                float z4b = acc[i + 2][j][3] + b2b;
                float2 gw;
                gw.x = z3a / (1.f + expf(-z4a));
                gw.y = z3b / (1.f + expf(-z4b));
                *(float2*)&g_buf0[((long)bb * 128 + ob) * 250 + l] = gw;
            }
        }
    }
}

// ---------------------------------------------------------------------------
// lw GEMM + stats (R13, sync-free resident).
__global__ void __launch_bounds__(256)
gemm_lw_mma(const float* __restrict__ bias) {
    extern __shared__ char dsm[];
    unsigned* Ghi = (unsigned*)dsm;
    unsigned* Glo = (unsigned*)(dsm + 34816);
    unsigned* Whi = (unsigned*)(dsm + 69632);
    unsigned* Wlo = (unsigned*)(dsm + 104448);
    float* sbias = (float*)(dsm + 139264);
    float* red = (float*)(dsm + 139776);

    int tid = threadIdx.x;
    int w = tid >> 5, lane = tid & 31;
    int g = lane >> 2, tg = lane & 3;
    int mw = w >> 1, nw = w & 1;
    long r0 = (long)blockIdx.x * 128;

    if (tid < 128) sbias[tid] = bias[tid];

    #pragma unroll
    for (int p = 0; p < 8; ++p) {
        int i = tid + p * 256;
        int c = i >> 4, q = i & 15;
        uint4 vh = ((const uint4*)g_lwWhi)[c * 16 + q];
        uint4 vl = ((const uint4*)g_lwWlo)[c * 16 + q];
        *(uint4*)&Whi[c * 68 + q * 4] = vh;
        *(uint4*)&Wlo[c * 68 + q * 4] = vl;
    }

    #pragma unroll
    for (int p = 0; p < 32; ++p) {
        int i = tid + p * 256;
        int r = i >> 6, kk = i & 63;
        long row = r0 + r; if (row >= NCOL) row = NCOL - 1;
        float2 v = *(const float2*)&g_buf0[row * 128 + kk * 2];
        __nv_bfloat16 h0 = __float2bfloat16(v.x);
        __nv_bfloat16 h1 = __float2bfloat16(v.y);
        __nv_bfloat16 l0 = __float2bfloat16(v.x - __bfloat162float(h0));
        __nv_bfloat16 l1 = __float2bfloat16(v.y - __bfloat162float(h1));
        Ghi[r * 68 + kk] = pkbf(h0, h1);
        Glo[r * 68 + kk] = pkbf(l0, l1);
    }
    __syncthreads();

    unsigned aAddr = smem_u32p(Ghi)
        + (((lane & 7) + ((lane >> 3) & 1) * 8 + mw * 32) * 68 + (lane >> 4) * 4) * 4;
    unsigned bAddr = smem_u32p(Whi)
        + ((lane & 7) + (lane >> 4) * 8 + nw * 64) * 272 + ((lane >> 3) & 1) * 16;

    float acc[2][8][4];
    #pragma unroll
    for (int i = 0; i < 2; ++i)
        #pragma unroll
        for (int j = 0; j < 8; ++j)
            #pragma unroll
            for (int q = 0; q < 4; ++q) acc[i][j][q] = 0.f;

    #pragma unroll
    for (int ks = 0; ks < 24; ++ks) {
        unsigned aoff = (ks < 16) ? (unsigned)(ks & 7) * 32u
                                  : 34816u + (unsigned)(ks - 16) * 32u;
        unsigned boff = (ks < 8) ? (unsigned)ks * 32u
                      : (ks < 16) ? 34816u + (unsigned)(ks - 8) * 32u
                                  : (unsigned)(ks - 16) * 32u;
        unsigned bf0[8], bf1[8];
        #pragma unroll
        for (int jp = 0; jp < 4; ++jp)
            ldm4(bf0[2 * jp], bf1[2 * jp], bf0[2 * jp + 1], bf1[2 * jp + 1],
                 bAddr + jp * 16 * 272 + boff);
        #pragma unroll
        for (int i = 0; i < 2; ++i) {
            unsigned a0, a1, a2, a3;
            ldm4(a0, a1, a2, a3, aAddr + aoff + i * 16 * 272);
            #pragma unroll
            for (int j = 0; j < 8; ++j)
                mma16816(acc[i][j][0], acc[i][j][1], acc[i][j][2], acc[i][j][3],
                         a0, a1, a2, a3, bf0[j], bf1[j]);
        }
    }

    int b0idx = (int)(r0 / 62500);
    float s0 = 0.f, q0 = 0.f, s1 = 0.f, q1 = 0.f;
    #pragma unroll
    for (int i = 0; i < 2; ++i) {
        long ra = r0 + mw * 32 + i * 16 + g;
        long rb = ra + 8;
        #pragma unroll
        for (int j = 0; j < 8; ++j) {
            int c = nw * 64 + j * 8 + tg * 2;
            float bv0 = sbias[c], bv1 = sbias[c + 1];
            if (ra < NCOL) {
                float v0 = acc[i][j][0] + bv0;
                float v1 = acc[i][j][1] + bv1;
                *(float2*)&g_buf1[ra * 128 + c] = make_float2(v0, v1);
                float rs = v0 + v1, rq = v0 * v0 + v1 * v1;
                if ((int)(ra / 62500) == b0idx) { s0 += rs; q0 += rq; }
                else                            { s1 += rs; q1 += rq; }
            }
            if (rb < NCOL) {
                float v2 = acc[i][j][2] + bv0;
                float v3 = acc[i][j][3] + bv1;
                *(float2*)&g_buf1[rb * 128 + c] = make_float2(v2, v3);
                float rs = v2 + v3, rq = v2 * v2 + v3 * v3;
                if ((int)(rb / 62500) == b0idx) { s0 += rs; q0 += rq; }
                else                            { s1 += rs; q1 += rq; }
            }
        }
    }
    #pragma unroll
    for (int off = 16; off; off >>= 1) {
        s0 += __shfl_down_sync(0xffffffffu, s0, off);
        q0 += __shfl_down_sync(0xffffffffu, q0, off);
        s1 += __shfl_down_sync(0xffffffffu, s1, off);
        q1 += __shfl_down_sync(0xffffffffu, q1, off);
    }
    if (lane == 0) { red[w * 4 + 0] = s0; red[w * 4 + 1] = q0; red[w * 4 + 2] = s1; red[w * 4 + 3] = q1; }
    __syncthreads();
    if (tid == 0) {
        float ts0 = 0.f, tq0 = 0.f, ts1 = 0.f, tq1 = 0.f;
        #pragma unroll
        for (int j = 0; j < 8; ++j) {
            ts0 += red[j * 4 + 0]; tq0 += red[j * 4 + 1];
            ts1 += red[j * 4 + 2]; tq1 += red[j * 4 + 3];
        }
        atomicAdd(&g_stats[2 * b0idx],     (double)ts0);
        atomicAdd(&g_stats[2 * b0idx + 1], (double)tq0);
        if (b0idx < 3) {
            atomicAdd(&g_stats[2 * b0idx + 2], (double)ts1);
            atomicAdd(&g_stats[2 * b0idx + 3], (double)tq1);
        }
    }
}

// ---------------------------------------------------------------------------
__global__ void zero_stats() {
    if (threadIdx.x < 8) g_stats[threadIdx.x] = 0.0;
}

__global__ void finalize_stats() {
    int b = threadIdx.x;
    if (b < 4) {
        double mu  = g_stats[2 * b] / (double)PERB;
        double var = g_stats[2 * b + 1] / (double)PERB - mu * mu;
        g_mu[b]  = (float)mu;
        g_inv[b] = (float)(1.0 / sqrt(var + 1e-8));
    }
}

__global__ void trans_norm_intra(const float* __restrict__ gg, const float* __restrict__ gb,
                                 const float* __restrict__ x, float* __restrict__ out) {
    __shared__ float tile[32][33];
    int bn = blockIdx.y;
    int b = bn >> 7, n = bn & 127;
    int tk = blockIdx.x & 7, ts = blockIdx.x >> 3;
    int s = ts * 32 + threadIdx.y;
    int k = tk * 32 + threadIdx.x;
    if (s < 250 && k < 250)
        tile[threadIdx.y][threadIdx.x] =
            g_buf1[((long)(b * 250 + s)) * 32000 + n * 250 + k];
    __syncthreads();
    int k2 = tk * 32 + threadIdx.y;
    int s2 = ts * 32 + threadIdx.x;
    if (k2 < 250 && s2 < 250) {
        float mu = g_mu[b], inv = g_inv[b];
        long oi = (((long)(b * 128 + n)) * 250 + k2) * 250 + s2;
        float val = (tile[threadIdx.x][threadIdx.y] - mu) * inv * gg[n] + gb[n] + x[oi];
        out[oi] = val;
        g_buf0[(((long)(b * 250 + k2)) * 128 + n) * 250 + s2] = val;
    }
}

__global__ void norm_final(const float* __restrict__ gg, const float* __restrict__ gb,
                           float* __restrict__ out) {
    int i = blockIdx.x * 256 + threadIdx.x;
    int s = i % 250;
    int t = i / 250;
    int k = t % 250; t /= 250;
    int n = t & 127;
    int b = t >> 7;
    float mu = g_mu[b], inv = g_inv[b];
    float v = g_buf1[((long)(b * 250 + k)) * 32000 + n * 250 + s];
    out[i] = (v - mu) * inv * gg[n] + gb[n] + out[i];
}

// ---------------------------------------------------------------------------
extern "C" void kernel_launch(void* const* d_in, const int* in_sizes, int n_in,
                              void* d_out, int out_size) {
    const float* x = (const float*)d_in[0];
    const float* ip[12];
    const float* pp[12];
    for (int j = 0; j < 12; ++j) ip[j] = (const float*)d_in[1 + j];
    for (int j = 0; j < 12; ++j) pp[j] = (const float*)d_in[13 + j];
    float* out = (float*)d_out;

    const int EB = TOT / 256;
    const int SMEM_OW = 190464;
    const int SMEM_LW = 139904;
    const int SMEM_CV = 204800;
    cudaFuncSetAttribute(gemm_ow_mma, cudaFuncAttributeMaxDynamicSharedMemorySize, SMEM_OW);
    cudaFuncSetAttribute(gemm_lw_mma, cudaFuncAttributeMaxDynamicSharedMemorySize, SMEM_LW);
    cudaFuncSetAttribute(conv_mma,    cudaFuncAttributeMaxDynamicSharedMemorySize, SMEM_CV);
    const int GOW = (NCOL + 63) / 64;   // 3907
    const int GUC = 64000;

    // ---- intra path ----
    pack_intra<<<dim3(64, 512), dim3(32, 32)>>>(x);
    kern_compute<<<NC, 256>>>(ip[0], ip[1], ip[2], ip[3], ip[4]);
    conv_u_bf16<<<GUC, 256>>>();
    conv_mma<<<dim3(32, 128), 256, SMEM_CV>>>(ip[5]);
    conv_ow_bf16<<<64, 256>>>(ip[6]);
    conv_lw_bf16<<<32, 256>>>(ip[8]);
    gemm_ow_mma<<<GOW, 256, SMEM_OW>>>(ip[7]);
    zero_stats<<<1, 32>>>();
    gemm_lw_mma<<<1954, 256, SMEM_LW>>>(ip[9]);
    finalize_stats<<<1, 32>>>();
    trans_norm_intra<<<dim3(64, 512), dim3(32, 32)>>>(ip[10], ip[11], x, out);

    // ---- inter path ----
    kern_compute<<<NC, 256>>>(pp[0], pp[1], pp[2], pp[3], pp[4]);
    conv_u_bf16<<<GUC, 256>>>();
    conv_mma<<<dim3(32, 128), 256, SMEM_CV>>>(pp[5]);
    conv_ow_bf16<<<64, 256>>>(pp[6]);
    conv_lw_bf16<<<32, 256>>>(pp[8]);
    gemm_ow_mma<<<GOW, 256, SMEM_OW>>>(pp[7]);
    zero_stats<<<1, 32>>>();
    gemm_lw_mma<<<1954, 256, SMEM_LW>>>(pp[9]);
    finalize_stats<<<1, 32>>>();
    norm_final<<<EB, 256>>>(pp[10], pp[11], out);
}

// round 16
// speedup vs baseline: 1.0926x; 1.0926x over previous
#include <cuda_runtime.h>
#include <cuda_bf16.h>
#include <math.h>

#define NC    128
#define LL    250
#define MM    32
#define NCOL  250000
#define TOT   32000000
#define PERB  8000000
#define PITCH 132

// Scratch
__device__ float g_buf0[32000000];  // u packed (intra) -> G (glu out, flat)
__device__ float g_buf1[32000000];  // yT -> Lf (lw out, flat)
__device__ float g_kern[NC * LL];
__device__ double g_stats[8];
__device__ float g_mu[4], g_inv[4];
__device__ unsigned g_owAhi[256 * 64];
__device__ unsigned g_owAlo[256 * 64];
__device__ unsigned g_lwWhi[128 * 64];
__device__ unsigned g_lwWlo[128 * 64];

// ---------------------------------------------------------------------------
typedef unsigned long long u64;
__device__ __forceinline__ u64 dup2(float x) {
    u64 r; asm("mov.b64 %0,{%1,%1};" : "=l"(r) : "f"(x)); return r;
}
__device__ __forceinline__ u64 pk2(float x, float y) {
    u64 r; asm("mov.b64 %0,{%1,%2};" : "=l"(r) : "f"(x), "f"(y)); return r;
}
__device__ __forceinline__ void fma2(u64& a, u64 b, u64 c) {
    asm("fma.rn.f32x2 %0,%1,%2,%0;" : "+l"(a) : "l"(b), "l"(c));
}
__device__ __forceinline__ void un2(u64 v, float& x, float& y) {
    asm("mov.b64 {%0,%1},%2;" : "=f"(x), "=f"(y) : "l"(v));
}
__device__ __forceinline__ void mma16816(float& c0, float& c1, float& c2, float& c3,
                                         unsigned a0, unsigned a1, unsigned a2, unsigned a3,
                                         unsigned b0, unsigned b1) {
    asm volatile(
        "mma.sync.aligned.m16n8k16.row.col.f32.bf16.bf16.f32 "
        "{%0,%1,%2,%3}, {%4,%5,%6,%7}, {%8,%9}, {%0,%1,%2,%3};"
        : "+f"(c0), "+f"(c1), "+f"(c2), "+f"(c3)
        : "r"(a0), "r"(a1), "r"(a2), "r"(a3), "r"(b0), "r"(b1));
}
__device__ __forceinline__ void ldm4(unsigned& r0, unsigned& r1, unsigned& r2, unsigned& r3,
                                     unsigned a) {
    asm volatile("ldmatrix.sync.aligned.m8n8.x4.shared.b16 {%0,%1,%2,%3}, [%4];"
        : "=r"(r0), "=r"(r1), "=r"(r2), "=r"(r3) : "r"(a));
}
__device__ __forceinline__ unsigned pkbf(__nv_bfloat16 a, __nv_bfloat16 b) {
    unsigned r;
    asm("mov.b32 %0, {%1, %2};" : "=r"(r)
        : "h"(*(unsigned short*)&a), "h"(*(unsigned short*)&b));
    return r;
}
__device__ __forceinline__ unsigned smem_u32p(const void* p) {
    return (unsigned)__cvta_generic_to_shared(p);
}

// ---------------------------------------------------------------------------
__global__ void pack_intra(const float* __restrict__ x) {
    __shared__ float tile[32][33];
    int bh = blockIdx.y;
    int b = bh >> 7, h = bh & 127;
    int tk = blockIdx.x & 7;
    int ts = blockIdx.x >> 3;
    int k = tk * 32 + threadIdx.y;
    int s = ts * 32 + threadIdx.x;
    if (k < 250 && s < 250)
        tile[threadIdx.y][threadIdx.x] = x[(((long)bh * 250 + k) * 250) + s];
    __syncthreads();
    int s2 = ts * 32 + threadIdx.y;
    int k2 = tk * 32 + threadIdx.x;
    if (s2 < 250 && k2 < 250)
        g_buf0[(((long)(b * 250 + s2) * 128 + h) * 250) + k2] = tile[threadIdx.x][threadIdx.y];
}

// ---------------------------------------------------------------------------
__global__ void kern_compute(const float* __restrict__ log_dt,
                             const float* __restrict__ logA_re,
                             const float* __restrict__ A_im,
                             const float* __restrict__ C_re,
                             const float* __restrict__ C_im) {
    __shared__ float sCr[MM], sCi[MM], sar[MM], sai[MM];
    int h = blockIdx.x;
    int t = threadIdx.x;
    if (t < MM) {
        float dt  = expf(log_dt[h]);
        float Are = -expf(logA_re[h * MM + t]);
        float Aim = A_im[h * MM + t];
        float ar = dt * Are, ai = dt * Aim;
        float ea = expf(ar);
        float sb, cb; sincosf(ai, &sb, &cb);
        float er = ea * cb - 1.f, ei = ea * sb;
        float den = Are * Are + Aim * Aim;
        float qr = (er * Are + ei * Aim) / den;
        float qi = (ei * Are - er * Aim) / den;
        float cr = C_re[h * MM + t], ci = C_im[h * MM + t];
        sCr[t] = cr * qr - ci * qi;
        sCi[t] = cr * qi + ci * qr;
        sar[t] = ar; sai[t] = ai;
    }
    __syncthreads();
    if (t < LL) {
        float fl = (float)t;
        float sum = 0.f;
        #pragma unroll
        for (int m = 0; m < MM; ++m) {
            float ea = expf(sar[m] * fl);
            float sb, cb; sincosf(sai[m] * fl, &sb, &cb);
            sum += ea * (sCr[m] * cb - sCi[m] * sb);
        }
        g_kern[h * LL + t] = 2.f * sum;
    }
}

// ---------------------------------------------------------------------------
// Conv as per-h Toeplitz GEMM + GELU, f32x2. D folded into kern[0].
// mode 0 (intra): u from g_buf0 packed: (bb*128+h)*250 + m
// mode 1 (inter): u from src=out[b][h][k][s]: (((bb/250)*128+h)*250 + bb%250)*250 + m
__global__ void __launch_bounds__(256, 2)
conv_gemm(const float* __restrict__ D, const float* __restrict__ src, int mode) {
    __shared__ float As[32 * PITCH];
    __shared__ float Bs[32 * PITCH];
    __shared__ float skp[512];
    int tid = threadIdx.x;
    int h = blockIdx.y;
    int rowblk = blockIdx.x >> 1, colblk = blockIdx.x & 1;
    int r0 = rowblk * 128;
    int t0 = colblk * 128;
    int nkt = colblk ? 8 : 4;

    {
        float kv = (tid < 250) ? g_kern[h * 250 + tid] : 0.f;
        if (tid == 0) kv += D[h];            // fold D*u into k[0]
        skp[tid] = 0.f;
        skp[256 + tid] = kv;
    }
    __syncthreads();

    const float* usrc = (mode == 0) ? (const float*)g_buf0 : src;

    int tx = tid & 15, ty = tid >> 4;
    u64 acc[8][4];
    #pragma unroll
    for (int i = 0; i < 8; ++i)
        #pragma unroll
        for (int j = 0; j < 4; ++j) acc[i][j] = 0ull;

    for (int kt = 0; kt < nkt; ++kt) {
        int m0 = kt * 32;
        {
            int c4 = (tid & 7) * 4;
            int rb = tid >> 3;
            #pragma unroll
            for (int p = 0; p < 4; ++p) {
                int r = rb + p * 32;
                int bb = r0 + r; if (bb > 999) bb = 999;
                long base;
                if (mode == 0) {
                    base = ((long)bb * 128 + h) * 250;
                } else {
                    int b = bb / 250, kk = bb - b * 250;
                    base = (((long)(b * 128 + h)) * 250 + kk) * 250;
                }
                const float* up = usrc + base + m0 + c4;
                float2 v0 = (m0 + c4     < 250) ? *(const float2*)(up)     : make_float2(0.f, 0.f);
                float2 v1 = (m0 + c4 + 2 < 250) ? *(const float2*)(up + 2) : make_float2(0.f, 0.f);
                As[(c4 + 0) * PITCH + r] = v0.x; As[(c4 + 1) * PITCH + r] = v0.y;
                As[(c4 + 2) * PITCH + r] = v1.x; As[(c4 + 3) * PITCH + r] = v1.y;
            }
        }
        {
            int mm = tid >> 3;
            int ttb = (tid & 7) * 16;
            int base = 256 + t0 - m0 - mm + ttb;
            #pragma unroll
            for (int q = 0; q < 16; ++q)
                Bs[mm * PITCH + ttb + q] = skp[base + q];
        }
        __syncthreads();
        #pragma unroll
        for (int kk = 0; kk < 32; ++kk) {
            float4 a0 = *(const float4*)&As[kk * PITCH + ty * 8];
            float4 a1 = *(const float4*)&As[kk * PITCH + ty * 8 + 4];
            float4 b0 = *(const float4*)&Bs[kk * PITCH + tx * 8];
            float4 b1 = *(const float4*)&Bs[kk * PITCH + tx * 8 + 4];
            u64 ad[8] = {dup2(a0.x), dup2(a0.y), dup2(a0.z), dup2(a0.w),
                         dup2(a1.x), dup2(a1.y), dup2(a1.z), dup2(a1.w)};
            u64 bp4[4] = {pk2(b0.x, b0.y), pk2(b0.z, b0.w),
                          pk2(b1.x, b1.y), pk2(b1.z, b1.w)};
            #pragma unroll
            for (int i = 0; i < 8; ++i)
                #pragma unroll
                for (int j = 0; j < 4; ++j)
                    fma2(acc[i][j], ad[i], bp4[j]);
        }
        __syncthreads();
    }

    // Epilogue: pure GELU + store (D already folded).
    #pragma unroll
    for (int i = 0; i < 8; ++i) {
        int bb = r0 + ty * 8 + i;
        if (bb > 999) continue;
        float c[8];
        #pragma unroll
        for (int j = 0; j < 4; ++j) un2(acc[i][j], c[2 * j], c[2 * j + 1]);
        int tbase = t0 + tx * 8;
        float* yp = g_buf1 + (long)h * NCOL + (long)bb * 250 + tbase;
        #pragma unroll
        for (int j2 = 0; j2 < 4; ++j2) {
            int t = tbase + 2 * j2;
            if (t < 250) {
                float y0 = c[2 * j2];
                float y1 = c[2 * j2 + 1];
                float e0 = y0 + 0.044715f * y0 * y0 * y0;
                float e1 = y1 + 0.044715f * y1 * y1 * y1;
                float2 g;
                g.x = 0.5f * y0 * (1.f + tanhf(0.7978845608f * e0));
                g.y = 0.5f * y1 * (1.f + tanhf(0.7978845608f * e1));
                *(float2*)(yp + 2 * j2) = g;
            }
        }
    }
}

// ---------------------------------------------------------------------------
// Merged weight pre-convert: blocks 0..63 -> ow (256x128), 64..95 -> lw (128x128)
__global__ void conv_w_bf16(const float* __restrict__ ow, const float* __restrict__ lw) {
    int blk = blockIdx.x;
    if (blk < 64) {
        int idx = blk * 256 + threadIdx.x;
        int o = idx >> 6, kp = idx & 63;
        float v0 = ow[o * 128 + kp * 2];
        float v1 = ow[o * 128 + kp * 2 + 1];
        __nv_bfloat16 h0 = __float2bfloat16(v0);
        __nv_bfloat16 h1 = __float2bfloat16(v1);
        __nv_bfloat16 l0 = __float2bfloat16(v0 - __bfloat162float(h0));
        __nv_bfloat16 l1 = __float2bfloat16(v1 - __bfloat162float(h1));
        g_owAhi[o * 64 + kp] = pkbf(h0, h1);
        g_owAlo[o * 64 + kp] = pkbf(l0, l1);
    } else {
        int idx = (blk - 64) * 256 + threadIdx.x;
        int c = idx >> 6, kp = idx & 63;
        float v0 = lw[c * 128 + kp * 2];
        float v1 = lw[c * 128 + kp * 2 + 1];
        __nv_bfloat16 h0 = __float2bfloat16(v0);
        __nv_bfloat16 h1 = __float2bfloat16(v1);
        __nv_bfloat16 l0 = __float2bfloat16(v0 - __bfloat162float(h0));
        __nv_bfloat16 l1 = __float2bfloat16(v1 - __bfloat162float(h1));
        g_lwWhi[c * 64 + kp] = pkbf(h0, h1);
        g_lwWlo[c * 64 + kp] = pkbf(l0, l1);
    }
}

// ---------------------------------------------------------------------------
// ow GEMM + GLU: fully smem-resident operands, sync-free mainloop (R13).
__global__ void __launch_bounds__(256)
gemm_ow_mma(const float* __restrict__ bias) {
    extern __shared__ char dsm[];
    unsigned* Ahi = (unsigned*)dsm;
    __nv_bfloat16* Bs16 = (__nv_bfloat16*)(dsm + 139264);
    float* sbias = (float*)(dsm + 189440);

    int tid = threadIdx.x;
    int w = tid >> 5, lane = tid & 31;
    int g = lane >> 2, tg = lane & 3;
    int mw = w >> 1, nw = w & 1;
    long n0 = (long)blockIdx.x * 64;

    sbias[tid] = bias[tid];

    #pragma unroll
    for (int p = 0; p < 16; ++p) {
        int i = tid + p * 256;
        int o = i >> 4, q = i & 15;
        uint4 vh = ((const uint4*)g_owAhi)[o * 16 + q];
        uint4 vl = ((const uint4*)g_owAlo)[o * 16 + q];
        *(uint4*)&Ahi[o * 68 + q * 4] = vh;
        *(uint4*)(dsm + 69632 + (o * 68 + q * 4) * 4) = vl;
    }

    for (int i = tid; i < 128 * 64; i += 256) {
        int hk = i >> 6, c = i & 63;
        long col = n0 + c; if (col >= NCOL) col = NCOL - 1;
        float v = g_buf1[(long)hk * NCOL + col];
        __nv_bfloat16 hi = __float2bfloat16(v);
        __nv_bfloat16 lo = __float2bfloat16(v - __bfloat162float(hi));
        __nv_bfloat16* bp = Bs16 + c * 392;
        bp[hk] = hi; bp[hk + 128] = lo; bp[hk + 256] = hi;
    }
    __syncthreads();

    unsigned aAddr = smem_u32p(Ahi)
        + (((lane & 7) + ((lane >> 3) & 1) * 8 + mw * 32) * 68 + (lane >> 4) * 4) * 4;
    unsigned bAddr = smem_u32p(Bs16)
        + ((lane & 7) + (lane >> 4) * 8 + nw * 32) * 784 + ((lane >> 3) & 1) * 16;

    float acc[4][4][4];
    #pragma unroll
    for (int i = 0; i < 4; ++i)
        #pragma unroll
        for (int j = 0; j < 4; ++j)
            #pragma unroll
            for (int q = 0; q < 4; ++q) acc[i][j][q] = 0.f;

    const unsigned tOff[4] = {0u, 16u * 272u, 128u * 272u, 144u * 272u};

    #pragma unroll
    for (int ks = 0; ks < 24; ++ks) {
        unsigned aoff = (ks < 16) ? (unsigned)(ks & 7) * 32u
                                  : 69632u + (unsigned)(ks - 16) * 32u;
        unsigned bf0[4], bf1[4];
        #pragma unroll
        for (int jp = 0; jp < 2; ++jp)
            ldm4(bf0[2 * jp], bf1[2 * jp], bf0[2 * jp + 1], bf1[2 * jp + 1],
                 bAddr + jp * 16 * 784 + ks * 32);
        #pragma unroll
        for (int i = 0; i < 4; ++i) {
            unsigned a0, a1, a2, a3;
            ldm4(a0, a1, a2, a3, aAddr + tOff[i] + aoff);
            #pragma unroll
            for (int j = 0; j < 4; ++j)
                mma16816(acc[i][j][0], acc[i][j][1], acc[i][j][2], acc[i][j][3],
                         a0, a1, a2, a3, bf0[j], bf1[j]);
        }
    }

    #pragma unroll
    for (int i = 0; i < 2; ++i) {
        int oa = mw * 32 + i * 16 + g;
        int ob = oa + 8;
        float b1a = sbias[oa],       b1b = sbias[ob];
        float b2a = sbias[128 + oa], b2b = sbias[128 + ob];
        #pragma unroll
        for (int j = 0; j < 4; ++j) {
            int cl = nw * 32 + j * 8 + tg * 2;
            long col = n0 + cl;
            if (col < NCOL) {
                int bb = (int)(col / 250);
                int l  = (int)(col - (long)bb * 250);
                float z1a = acc[i][j][0] + b1a;
                float z1b = acc[i][j][1] + b1a;
                float z2a = acc[i + 2][j][0] + b2a;
                float z2b = acc[i + 2][j][1] + b2a;
                float2 gv;
                gv.x = z1a / (1.f + expf(-z2a));
                gv.y = z1b / (1.f + expf(-z2b));
                *(float2*)&g_buf0[((long)bb * 128 + oa) * 250 + l] = gv;
                float z3a = acc[i][j][2] + b1b;
                float z3b = acc[i][j][3] + b1b;
                float z4a = acc[i + 2][j][2] + b2b;
                float z4b = acc[i + 2][j][3] + b2b;
                float2 gw;
                gw.x = z3a / (1.f + expf(-z4a));
                gw.y = z3b / (1.f + expf(-z4b));
                *(float2*)&g_buf0[((long)bb * 128 + ob) * 250 + l] = gw;
            }
        }
    }
}

// ---------------------------------------------------------------------------
// lw GEMM + stats (R13, sync-free resident).
__global__ void __launch_bounds__(256)
gemm_lw_mma(const float* __restrict__ bias) {
    extern __shared__ char dsm[];
    unsigned* Ghi = (unsigned*)dsm;
    unsigned* Glo = (unsigned*)(dsm + 34816);
    unsigned* Whi = (unsigned*)(dsm + 69632);
    unsigned* Wlo = (unsigned*)(dsm + 104448);
    float* sbias = (float*)(dsm + 139264);
    float* red = (float*)(dsm + 139776);

    int tid = threadIdx.x;
    int w = tid >> 5, lane = tid & 31;
    int g = lane >> 2, tg = lane & 3;
    int mw = w >> 1, nw = w & 1;
    long r0 = (long)blockIdx.x * 128;

    if (tid < 128) sbias[tid] = bias[tid];

    #pragma unroll
    for (int p = 0; p < 8; ++p) {
        int i = tid + p * 256;
        int c = i >> 4, q = i & 15;
        uint4 vh = ((const uint4*)g_lwWhi)[c * 16 + q];
        uint4 vl = ((const uint4*)g_lwWlo)[c * 16 + q];
        *(uint4*)&Whi[c * 68 + q * 4] = vh;
        *(uint4*)&Wlo[c * 68 + q * 4] = vl;
    }

    #pragma unroll
    for (int p = 0; p < 32; ++p) {
        int i = tid + p * 256;
        int r = i >> 6, kk = i & 63;
        long row = r0 + r; if (row >= NCOL) row = NCOL - 1;
        float2 v = *(const float2*)&g_buf0[row * 128 + kk * 2];
        __nv_bfloat16 h0 = __float2bfloat16(v.x);
        __nv_bfloat16 h1 = __float2bfloat16(v.y);
        __nv_bfloat16 l0 = __float2bfloat16(v.x - __bfloat162float(h0));
        __nv_bfloat16 l1 = __float2bfloat16(v.y - __bfloat162float(h1));
        Ghi[r * 68 + kk] = pkbf(h0, h1);
        Glo[r * 68 + kk] = pkbf(l0, l1);
    }
    __syncthreads();

    unsigned aAddr = smem_u32p(Ghi)
        + (((lane & 7) + ((lane >> 3) & 1) * 8 + mw * 32) * 68 + (lane >> 4) * 4) * 4;
    unsigned bAddr = smem_u32p(Whi)
        + ((lane & 7) + (lane >> 4) * 8 + nw * 64) * 272 + ((lane >> 3) & 1) * 16;

    float acc[2][8][4];
    #pragma unroll
    for (int i = 0; i < 2; ++i)
        #pragma unroll
        for (int j = 0; j < 8; ++j)
            #pragma unroll
            for (int q = 0; q < 4; ++q) acc[i][j][q] = 0.f;

    #pragma unroll
    for (int ks = 0; ks < 24; ++ks) {
        unsigned aoff = (ks < 16) ? (unsigned)(ks & 7) * 32u
                                  : 34816u + (unsigned)(ks - 16) * 32u;
        unsigned boff = (ks < 8) ? (unsigned)ks * 32u
                      : (ks < 16) ? 34816u + (unsigned)(ks - 8) * 32u
                                  : (unsigned)(ks - 16) * 32u;
        unsigned bf0[8], bf1[8];
        #pragma unroll
        for (int jp = 0; jp < 4; ++jp)
            ldm4(bf0[2 * jp], bf1[2 * jp], bf0[2 * jp + 1], bf1[2 * jp + 1],
                 bAddr + jp * 16 * 272 + boff);
        #pragma unroll
        for (int i = 0; i < 2; ++i) {
            unsigned a0, a1, a2, a3;
            ldm4(a0, a1, a2, a3, aAddr + aoff + i * 16 * 272);
            #pragma unroll
            for (int j = 0; j < 8; ++j)
                mma16816(acc[i][j][0], acc[i][j][1], acc[i][j][2], acc[i][j][3],
                         a0, a1, a2, a3, bf0[j], bf1[j]);
        }
    }

    int b0idx = (int)(r0 / 62500);
    float s0 = 0.f, q0 = 0.f, s1 = 0.f, q1 = 0.f;
    #pragma unroll
    for (int i = 0; i < 2; ++i) {
        long ra = r0 + mw * 32 + i * 16 + g;
        long rb = ra + 8;
        #pragma unroll
        for (int j = 0; j < 8; ++j) {
            int c = nw * 64 + j * 8 + tg * 2;
            float bv0 = sbias[c], bv1 = sbias[c + 1];
            if (ra < NCOL) {
                float v0 = acc[i][j][0] + bv0;
                float v1 = acc[i][j][1] + bv1;
                *(float2*)&g_buf1[ra * 128 + c] = make_float2(v0, v1);
                float rs = v0 + v1, rq = v0 * v0 + v1 * v1;
                if ((int)(ra / 62500) == b0idx) { s0 += rs; q0 += rq; }
                else                            { s1 += rs; q1 += rq; }
            }
            if (rb < NCOL) {
                float v2 = acc[i][j][2] + bv0;
                float v3 = acc[i][j][3] + bv1;
                *(float2*)&g_buf1[rb * 128 + c] = make_float2(v2, v3);
                float rs = v2 + v3, rq = v2 * v2 + v3 * v3;
                if ((int)(rb / 62500) == b0idx) { s0 += rs; q0 += rq; }
                else                            { s1 += rs; q1 += rq; }
            }
        }
    }
    #pragma unroll
    for (int off = 16; off; off >>= 1) {
        s0 += __shfl_down_sync(0xffffffffu, s0, off);
        q0 += __shfl_down_sync(0xffffffffu, q0, off);
        s1 += __shfl_down_sync(0xffffffffu, s1, off);
        q1 += __shfl_down_sync(0xffffffffu, q1, off);
    }
    if (lane == 0) { red[w * 4 + 0] = s0; red[w * 4 + 1] = q0; red[w * 4 + 2] = s1; red[w * 4 + 3] = q1; }
    __syncthreads();
    if (tid == 0) {
        float ts0 = 0.f, tq0 = 0.f, ts1 = 0.f, tq1 = 0.f;
        #pragma unroll
        for (int j = 0; j < 8; ++j) {
            ts0 += red[j * 4 + 0]; tq0 += red[j * 4 + 1];
            ts1 += red[j * 4 + 2]; tq1 += red[j * 4 + 3];
        }
        atomicAdd(&g_stats[2 * b0idx],     (double)ts0);
        atomicAdd(&g_stats[2 * b0idx + 1], (double)tq0);
        if (b0idx < 3) {
            atomicAdd(&g_stats[2 * b0idx + 2], (double)ts1);
            atomicAdd(&g_stats[2 * b0idx + 3], (double)tq1);
        }
    }
}

// ---------------------------------------------------------------------------
__global__ void zero_stats() {
    if (threadIdx.x < 8) g_stats[threadIdx.x] = 0.0;
}

__global__ void finalize_stats() {
    int b = threadIdx.x;
    if (b < 4) {
        double mu  = g_stats[2 * b] / (double)PERB;
        double var = g_stats[2 * b + 1] / (double)PERB - mu * mu;
        g_mu[b]  = (float)mu;
        g_inv[b] = (float)(1.0 / sqrt(var + 1e-8));
    }
}

// intra: transpose + norm + residual; inter conv reads `out` directly.
__global__ void trans_norm_intra(const float* __restrict__ gg, const float* __restrict__ gb,
                                 const float* __restrict__ x, float* __restrict__ out) {
    __shared__ float tile[32][33];
    int bn = blockIdx.y;
    int b = bn >> 7, n = bn & 127;
    int tk = blockIdx.x & 7, ts = blockIdx.x >> 3;
    int s = ts * 32 + threadIdx.y;
    int k = tk * 32 + threadIdx.x;
    if (s < 250 && k < 250)
        tile[threadIdx.y][threadIdx.x] =
            g_buf1[((long)(b * 250 + s)) * 32000 + n * 250 + k];
    __syncthreads();
    int k2 = tk * 32 + threadIdx.y;
    int s2 = ts * 32 + threadIdx.x;
    if (k2 < 250 && s2 < 250) {
        float mu = g_mu[b], inv = g_inv[b];
        long oi = (((long)(b * 128 + n)) * 250 + k2) * 250 + s2;
        float val = (tile[threadIdx.x][threadIdx.y] - mu) * inv * gg[n] + gb[n] + x[oi];
        out[oi] = val;
    }
}

__global__ void norm_final(const float* __restrict__ gg, const float* __restrict__ gb,
                           float* __restrict__ out) {
    int i = blockIdx.x * 256 + threadIdx.x;
    int s = i % 250;
    int t = i / 250;
    int k = t % 250; t /= 250;
    int n = t & 127;
    int b = t >> 7;
    float mu = g_mu[b], inv = g_inv[b];
    float v = g_buf1[((long)(b * 250 + k)) * 32000 + n * 250 + s];
    out[i] = (v - mu) * inv * gg[n] + gb[n] + out[i];
}

// ---------------------------------------------------------------------------
extern "C" void kernel_launch(void* const* d_in, const int* in_sizes, int n_in,
                              void* d_out, int out_size) {
    const float* x = (const float*)d_in[0];
    const float* ip[12];
    const float* pp[12];
    for (int j = 0; j < 12; ++j) ip[j] = (const float*)d_in[1 + j];
    for (int j = 0; j < 12; ++j) pp[j] = (const float*)d_in[13 + j];
    float* out = (float*)d_out;

    const int EB = TOT / 256;
    const int SMEM_OW = 190464;
    const int SMEM_LW = 139904;
    cudaFuncSetAttribute(gemm_ow_mma, cudaFuncAttributeMaxDynamicSharedMemorySize, SMEM_OW);
    cudaFuncSetAttribute(gemm_lw_mma, cudaFuncAttributeMaxDynamicSharedMemorySize, SMEM_LW);
    const int GOW = (NCOL + 63) / 64;   // 3907

    // ---- intra path ----
    pack_intra<<<dim3(64, 512), dim3(32, 32)>>>(x);
    kern_compute<<<NC, 256>>>(ip[0], ip[1], ip[2], ip[3], ip[4]);
    conv_gemm<<<dim3(16, 128), 256>>>(ip[5], (const float*)0, 0);
    conv_w_bf16<<<96, 256>>>(ip[6], ip[8]);
    gemm_ow_mma<<<GOW, 256, SMEM_OW>>>(ip[7]);
    zero_stats<<<1, 32>>>();
    gemm_lw_mma<<<1954, 256, SMEM_LW>>>(ip[9]);
    finalize_stats<<<1, 32>>>();
    trans_norm_intra<<<dim3(64, 512), dim3(32, 32)>>>(ip[10], ip[11], x, out);

    // ---- inter path ----
    kern_compute<<<NC, 256>>>(pp[0], pp[1], pp[2], pp[3], pp[4]);
    conv_gemm<<<dim3(16, 128), 256>>>(pp[5], out, 1);
    conv_w_bf16<<<96, 256>>>(pp[6], pp[8]);
    gemm_ow_mma<<<GOW, 256, SMEM_OW>>>(pp[7]);
    zero_stats<<<1, 32>>>();
    gemm_lw_mma<<<1954, 256, SMEM_LW>>>(pp[9]);
    finalize_stats<<<1, 32>>>();
    norm_final<<<EB, 256>>>(pp[10], pp[11], out);
}

// round 17
// speedup vs baseline: 1.1079x; 1.0139x over previous
#include <cuda_runtime.h>
#include <cuda_bf16.h>
#include <math.h>

#define NC    128
#define LL    250
#define MM    32
#define NCOL  250000
#define TOT   32000000
#define PERB  8000000
#define PITCH 132
#define NSM   148

// Scratch
__device__ float g_buf0[32000000];  // u packed (intra) -> G (glu out, flat)
__device__ float g_buf1[32000000];  // yT -> Lf (lw out, flat)
__device__ float g_kern[NC * LL];
__device__ double g_stats[8];
__device__ float g_mu[4], g_inv[4];
__device__ unsigned g_owAhi[256 * 64];
__device__ unsigned g_owAlo[256 * 64];
__device__ unsigned g_lwWhi[128 * 64];
__device__ unsigned g_lwWlo[128 * 64];

// ---------------------------------------------------------------------------
typedef unsigned long long u64;
__device__ __forceinline__ u64 dup2(float x) {
    u64 r; asm("mov.b64 %0,{%1,%1};" : "=l"(r) : "f"(x)); return r;
}
__device__ __forceinline__ u64 pk2(float x, float y) {
    u64 r; asm("mov.b64 %0,{%1,%2};" : "=l"(r) : "f"(x), "f"(y)); return r;
}
__device__ __forceinline__ void fma2(u64& a, u64 b, u64 c) {
    asm("fma.rn.f32x2 %0,%1,%2,%0;" : "+l"(a) : "l"(b), "l"(c));
}
__device__ __forceinline__ void un2(u64 v, float& x, float& y) {
    asm("mov.b64 {%0,%1},%2;" : "=f"(x), "=f"(y) : "l"(v));
}
__device__ __forceinline__ void mma16816(float& c0, float& c1, float& c2, float& c3,
                                         unsigned a0, unsigned a1, unsigned a2, unsigned a3,
                                         unsigned b0, unsigned b1) {
    asm volatile(
        "mma.sync.aligned.m16n8k16.row.col.f32.bf16.bf16.f32 "
        "{%0,%1,%2,%3}, {%4,%5,%6,%7}, {%8,%9}, {%0,%1,%2,%3};"
        : "+f"(c0), "+f"(c1), "+f"(c2), "+f"(c3)
        : "r"(a0), "r"(a1), "r"(a2), "r"(a3), "r"(b0), "r"(b1));
}
__device__ __forceinline__ void ldm4(unsigned& r0, unsigned& r1, unsigned& r2, unsigned& r3,
                                     unsigned a) {
    asm volatile("ldmatrix.sync.aligned.m8n8.x4.shared.b16 {%0,%1,%2,%3}, [%4];"
        : "=r"(r0), "=r"(r1), "=r"(r2), "=r"(r3) : "r"(a));
}
__device__ __forceinline__ unsigned pkbf(__nv_bfloat16 a, __nv_bfloat16 b) {
    unsigned r;
    asm("mov.b32 %0, {%1, %2};" : "=r"(r)
        : "h"(*(unsigned short*)&a), "h"(*(unsigned short*)&b));
    return r;
}
__device__ __forceinline__ unsigned smem_u32p(const void* p) {
    return (unsigned)__cvta_generic_to_shared(p);
}

// ---------------------------------------------------------------------------
__global__ void pack_intra(const float* __restrict__ x) {
    __shared__ float tile[32][33];
    int bh = blockIdx.y;
    int b = bh >> 7, h = bh & 127;
    int tk = blockIdx.x & 7;
    int ts = blockIdx.x >> 3;
    int k = tk * 32 + threadIdx.y;
    int s = ts * 32 + threadIdx.x;
    if (k < 250 && s < 250)
        tile[threadIdx.y][threadIdx.x] = x[(((long)bh * 250 + k) * 250) + s];
    __syncthreads();
    int s2 = ts * 32 + threadIdx.y;
    int k2 = tk * 32 + threadIdx.x;
    if (s2 < 250 && k2 < 250)
        g_buf0[(((long)(b * 250 + s2) * 128 + h) * 250) + k2] = tile[threadIdx.x][threadIdx.y];
}

// ---------------------------------------------------------------------------
__global__ void kern_compute(const float* __restrict__ log_dt,
                             const float* __restrict__ logA_re,
                             const float* __restrict__ A_im,
                             const float* __restrict__ C_re,
                             const float* __restrict__ C_im) {
    __shared__ float sCr[MM], sCi[MM], sar[MM], sai[MM];
    int h = blockIdx.x;
    int t = threadIdx.x;
    if (t < MM) {
        float dt  = expf(log_dt[h]);
        float Are = -expf(logA_re[h * MM + t]);
        float Aim = A_im[h * MM + t];
        float ar = dt * Are, ai = dt * Aim;
        float ea = expf(ar);
        float sb, cb; sincosf(ai, &sb, &cb);
        float er = ea * cb - 1.f, ei = ea * sb;
        float den = Are * Are + Aim * Aim;
        float qr = (er * Are + ei * Aim) / den;
        float qi = (ei * Are - er * Aim) / den;
        float cr = C_re[h * MM + t], ci = C_im[h * MM + t];
        sCr[t] = cr * qr - ci * qi;
        sCi[t] = cr * qi + ci * qr;
        sar[t] = ar; sai[t] = ai;
    }
    __syncthreads();
    if (t < LL) {
        float fl = (float)t;
        float sum = 0.f;
        #pragma unroll
        for (int m = 0; m < MM; ++m) {
            float ea = expf(sar[m] * fl);
            float sb, cb; sincosf(sai[m] * fl, &sb, &cb);
            sum += ea * (sCr[m] * cb - sCi[m] * sb);
        }
        g_kern[h * LL + t] = 2.f * sum;
    }
}

// ---------------------------------------------------------------------------
// Conv as per-h Toeplitz GEMM + GELU, f32x2. D folded into kern[0].
__global__ void __launch_bounds__(256, 2)
conv_gemm(const float* __restrict__ D, const float* __restrict__ src, int mode) {
    __shared__ float As[32 * PITCH];
    __shared__ float Bs[32 * PITCH];
    __shared__ float skp[512];
    int tid = threadIdx.x;
    int h = blockIdx.y;
    int rowblk = blockIdx.x >> 1, colblk = blockIdx.x & 1;
    int r0 = rowblk * 128;
    int t0 = colblk * 128;
    int nkt = colblk ? 8 : 4;

    {
        float kv = (tid < 250) ? g_kern[h * 250 + tid] : 0.f;
        if (tid == 0) kv += D[h];
        skp[tid] = 0.f;
        skp[256 + tid] = kv;
    }
    __syncthreads();

    const float* usrc = (mode == 0) ? (const float*)g_buf0 : src;

    int tx = tid & 15, ty = tid >> 4;
    u64 acc[8][4];
    #pragma unroll
    for (int i = 0; i < 8; ++i)
        #pragma unroll
        for (int j = 0; j < 4; ++j) acc[i][j] = 0ull;

    for (int kt = 0; kt < nkt; ++kt) {
        int m0 = kt * 32;
        {
            int c4 = (tid & 7) * 4;
            int rb = tid >> 3;
            #pragma unroll
            for (int p = 0; p < 4; ++p) {
                int r = rb + p * 32;
                int bb = r0 + r; if (bb > 999) bb = 999;
                long base;
                if (mode == 0) {
                    base = ((long)bb * 128 + h) * 250;
                } else {
                    int b = bb / 250, kk = bb - b * 250;
                    base = (((long)(b * 128 + h)) * 250 + kk) * 250;
                }
                const float* up = usrc + base + m0 + c4;
                float2 v0 = (m0 + c4     < 250) ? *(const float2*)(up)     : make_float2(0.f, 0.f);
                float2 v1 = (m0 + c4 + 2 < 250) ? *(const float2*)(up + 2) : make_float2(0.f, 0.f);
                As[(c4 + 0) * PITCH + r] = v0.x; As[(c4 + 1) * PITCH + r] = v0.y;
                As[(c4 + 2) * PITCH + r] = v1.x; As[(c4 + 3) * PITCH + r] = v1.y;
            }
        }
        {
            int mm = tid >> 3;
            int ttb = (tid & 7) * 16;
            int base = 256 + t0 - m0 - mm + ttb;
            #pragma unroll
            for (int q = 0; q < 16; ++q)
                Bs[mm * PITCH + ttb + q] = skp[base + q];
        }
        __syncthreads();
        #pragma unroll
        for (int kk = 0; kk < 32; ++kk) {
            float4 a0 = *(const float4*)&As[kk * PITCH + ty * 8];
            float4 a1 = *(const float4*)&As[kk * PITCH + ty * 8 + 4];
            float4 b0 = *(const float4*)&Bs[kk * PITCH + tx * 8];
            float4 b1 = *(const float4*)&Bs[kk * PITCH + tx * 8 + 4];
            u64 ad[8] = {dup2(a0.x), dup2(a0.y), dup2(a0.z), dup2(a0.w),
                         dup2(a1.x), dup2(a1.y), dup2(a1.z), dup2(a1.w)};
            u64 bp4[4] = {pk2(b0.x, b0.y), pk2(b0.z, b0.w),
                          pk2(b1.x, b1.y), pk2(b1.z, b1.w)};
            #pragma unroll
            for (int i = 0; i < 8; ++i)
                #pragma unroll
                for (int j = 0; j < 4; ++j)
                    fma2(acc[i][j], ad[i], bp4[j]);
        }
        __syncthreads();
    }

    #pragma unroll
    for (int i = 0; i < 8; ++i) {
        int bb = r0 + ty * 8 + i;
        if (bb > 999) continue;
        float c[8];
        #pragma unroll
        for (int j = 0; j < 4; ++j) un2(acc[i][j], c[2 * j], c[2 * j + 1]);
        int tbase = t0 + tx * 8;
        float* yp = g_buf1 + (long)h * NCOL + (long)bb * 250 + tbase;
        #pragma unroll
        for (int j2 = 0; j2 < 4; ++j2) {
            int t = tbase + 2 * j2;
            if (t < 250) {
                float y0 = c[2 * j2];
                float y1 = c[2 * j2 + 1];
                float e0 = y0 + 0.044715f * y0 * y0 * y0;
                float e1 = y1 + 0.044715f * y1 * y1 * y1;
                float2 g;
                g.x = 0.5f * y0 * (1.f + tanhf(0.7978845608f * e0));
                g.y = 0.5f * y1 * (1.f + tanhf(0.7978845608f * e1));
                *(float2*)(yp + 2 * j2) = g;
            }
        }
    }
}

// ---------------------------------------------------------------------------
__global__ void conv_w_bf16(const float* __restrict__ ow, const float* __restrict__ lw) {
    int blk = blockIdx.x;
    if (blk < 64) {
        int idx = blk * 256 + threadIdx.x;
        int o = idx >> 6, kp = idx & 63;
        float v0 = ow[o * 128 + kp * 2];
        float v1 = ow[o * 128 + kp * 2 + 1];
        __nv_bfloat16 h0 = __float2bfloat16(v0);
        __nv_bfloat16 h1 = __float2bfloat16(v1);
        __nv_bfloat16 l0 = __float2bfloat16(v0 - __bfloat162float(h0));
        __nv_bfloat16 l1 = __float2bfloat16(v1 - __bfloat162float(h1));
        g_owAhi[o * 64 + kp] = pkbf(h0, h1);
        g_owAlo[o * 64 + kp] = pkbf(l0, l1);
    } else {
        int idx = (blk - 64) * 256 + threadIdx.x;
        int c = idx >> 6, kp = idx & 63;
        float v0 = lw[c * 128 + kp * 2];
        float v1 = lw[c * 128 + kp * 2 + 1];
        __nv_bfloat16 h0 = __float2bfloat16(v0);
        __nv_bfloat16 h1 = __float2bfloat16(v1);
        __nv_bfloat16 l0 = __float2bfloat16(v0 - __bfloat162float(h0));
        __nv_bfloat16 l1 = __float2bfloat16(v1 - __bfloat162float(h1));
        g_lwWhi[c * 64 + kp] = pkbf(h0, h1);
        g_lwWlo[c * 64 + kp] = pkbf(l0, l1);
    }
}

// ---------------------------------------------------------------------------
// ow GEMM + GLU: persistent; weights loaded once, loop over column tiles.
__global__ void __launch_bounds__(256)
gemm_ow_mma(const float* __restrict__ bias) {
    extern __shared__ char dsm[];
    unsigned* Ahi = (unsigned*)dsm;
    __nv_bfloat16* Bs16 = (__nv_bfloat16*)(dsm + 139264);
    float* sbias = (float*)(dsm + 189440);

    int tid = threadIdx.x;
    int w = tid >> 5, lane = tid & 31;
    int g = lane >> 2, tg = lane & 3;
    int mw = w >> 1, nw = w & 1;

    sbias[tid] = bias[tid];

    // Weights once per block
    #pragma unroll
    for (int p = 0; p < 16; ++p) {
        int i = tid + p * 256;
        int o = i >> 4, q = i & 15;
        uint4 vh = ((const uint4*)g_owAhi)[o * 16 + q];
        uint4 vl = ((const uint4*)g_owAlo)[o * 16 + q];
        *(uint4*)&Ahi[o * 68 + q * 4] = vh;
        *(uint4*)(dsm + 69632 + (o * 68 + q * 4) * 4) = vl;
    }
    __syncthreads();

    unsigned aAddr = smem_u32p(Ahi)
        + (((lane & 7) + ((lane >> 3) & 1) * 8 + mw * 32) * 68 + (lane >> 4) * 4) * 4;
    unsigned bAddr = smem_u32p(Bs16)
        + ((lane & 7) + (lane >> 4) * 8 + nw * 32) * 784 + ((lane >> 3) & 1) * 16;
    const unsigned tOff[4] = {0u, 16u * 272u, 128u * 272u, 144u * 272u};

    for (int tileidx = blockIdx.x; tileidx < 3907; tileidx += gridDim.x) {
        long n0 = (long)tileidx * 64;

        // Build B3 from yT
        for (int i = tid; i < 128 * 64; i += 256) {
            int hk = i >> 6, c = i & 63;
            long col = n0 + c; if (col >= NCOL) col = NCOL - 1;
            float v = g_buf1[(long)hk * NCOL + col];
            __nv_bfloat16 hi = __float2bfloat16(v);
            __nv_bfloat16 lo = __float2bfloat16(v - __bfloat162float(hi));
            __nv_bfloat16* bp = Bs16 + c * 392;
            bp[hk] = hi; bp[hk + 128] = lo; bp[hk + 256] = hi;
        }
        __syncthreads();

        float acc[4][4][4];
        #pragma unroll
        for (int i = 0; i < 4; ++i)
            #pragma unroll
            for (int j = 0; j < 4; ++j)
                #pragma unroll
                for (int q = 0; q < 4; ++q) acc[i][j][q] = 0.f;

        #pragma unroll
        for (int ks = 0; ks < 24; ++ks) {
            unsigned aoff = (ks < 16) ? (unsigned)(ks & 7) * 32u
                                      : 69632u + (unsigned)(ks - 16) * 32u;
            unsigned bf0[4], bf1[4];
            #pragma unroll
            for (int jp = 0; jp < 2; ++jp)
                ldm4(bf0[2 * jp], bf1[2 * jp], bf0[2 * jp + 1], bf1[2 * jp + 1],
                     bAddr + jp * 16 * 784 + ks * 32);
            #pragma unroll
            for (int i = 0; i < 4; ++i) {
                unsigned a0, a1, a2, a3;
                ldm4(a0, a1, a2, a3, aAddr + tOff[i] + aoff);
                #pragma unroll
                for (int j = 0; j < 4; ++j)
                    mma16816(acc[i][j][0], acc[i][j][1], acc[i][j][2], acc[i][j][3],
                             a0, a1, a2, a3, bf0[j], bf1[j]);
            }
        }

        #pragma unroll
        for (int i = 0; i < 2; ++i) {
            int oa = mw * 32 + i * 16 + g;
            int ob = oa + 8;
            float b1a = sbias[oa],       b1b = sbias[ob];
            float b2a = sbias[128 + oa], b2b = sbias[128 + ob];
            #pragma unroll
            for (int j = 0; j < 4; ++j) {
                int cl = nw * 32 + j * 8 + tg * 2;
                long col = n0 + cl;
                if (col < NCOL) {
                    int bb = (int)(col / 250);
                    int l  = (int)(col - (long)bb * 250);
                    float z1a = acc[i][j][0] + b1a;
                    float z1b = acc[i][j][1] + b1a;
                    float z2a = acc[i + 2][j][0] + b2a;
                    float z2b = acc[i + 2][j][1] + b2a;
                    float2 gv;
                    gv.x = z1a / (1.f + expf(-z2a));
                    gv.y = z1b / (1.f + expf(-z2b));
                    *(float2*)&g_buf0[((long)bb * 128 + oa) * 250 + l] = gv;
                    float z3a = acc[i][j][2] + b1b;
                    float z3b = acc[i][j][3] + b1b;
                    float z4a = acc[i + 2][j][2] + b2b;
                    float z4b = acc[i + 2][j][3] + b2b;
                    float2 gw;
                    gw.x = z3a / (1.f + expf(-z4a));
                    gw.y = z3b / (1.f + expf(-z4b));
                    *(float2*)&g_buf0[((long)bb * 128 + ob) * 250 + l] = gw;
                }
            }
        }
        __syncthreads();   // protect Bs16 before next build
    }
}

// ---------------------------------------------------------------------------
// lw GEMM + stats: persistent; W loaded once, loop over row tiles.
__global__ void __launch_bounds__(256)
gemm_lw_mma(const float* __restrict__ bias) {
    extern __shared__ char dsm[];
    unsigned* Ghi = (unsigned*)dsm;
    unsigned* Glo = (unsigned*)(dsm + 34816);
    unsigned* Whi = (unsigned*)(dsm + 69632);
    unsigned* Wlo = (unsigned*)(dsm + 104448);
    float* sbias = (float*)(dsm + 139264);
    float* red = (float*)(dsm + 139776);

    int tid = threadIdx.x;
    int w = tid >> 5, lane = tid & 31;
    int g = lane >> 2, tg = lane & 3;
    int mw = w >> 1, nw = w & 1;

    if (tid < 128) sbias[tid] = bias[tid];

    #pragma unroll
    for (int p = 0; p < 8; ++p) {
        int i = tid + p * 256;
        int c = i >> 4, q = i & 15;
        uint4 vh = ((const uint4*)g_lwWhi)[c * 16 + q];
        uint4 vl = ((const uint4*)g_lwWlo)[c * 16 + q];
        *(uint4*)&Whi[c * 68 + q * 4] = vh;
        *(uint4*)&Wlo[c * 68 + q * 4] = vl;
    }
    __syncthreads();

    unsigned aAddr = smem_u32p(Ghi)
        + (((lane & 7) + ((lane >> 3) & 1) * 8 + mw * 32) * 68 + (lane >> 4) * 4) * 4;
    unsigned bAddr = smem_u32p(Whi)
        + ((lane & 7) + (lane >> 4) * 8 + nw * 64) * 272 + ((lane >> 3) & 1) * 16;

    for (int tileidx = blockIdx.x; tileidx < 1954; tileidx += gridDim.x) {
        long r0 = (long)tileidx * 128;

        #pragma unroll
        for (int p = 0; p < 32; ++p) {
            int i = tid + p * 256;
            int r = i >> 6, kk = i & 63;
            long row = r0 + r; if (row >= NCOL) row = NCOL - 1;
            float2 v = *(const float2*)&g_buf0[row * 128 + kk * 2];
            __nv_bfloat16 h0 = __float2bfloat16(v.x);
            __nv_bfloat16 h1 = __float2bfloat16(v.y);
            __nv_bfloat16 l0 = __float2bfloat16(v.x - __bfloat162float(h0));
            __nv_bfloat16 l1 = __float2bfloat16(v.y - __bfloat162float(h1));
            Ghi[r * 68 + kk] = pkbf(h0, h1);
            Glo[r * 68 + kk] = pkbf(l0, l1);
        }
        __syncthreads();

        float acc[2][8][4];
        #pragma unroll
        for (int i = 0; i < 2; ++i)
            #pragma unroll
            for (int j = 0; j < 8; ++j)
                #pragma unroll
                for (int q = 0; q < 4; ++q) acc[i][j][q] = 0.f;

        #pragma unroll
        for (int ks = 0; ks < 24; ++ks) {
            unsigned aoff = (ks < 16) ? (unsigned)(ks & 7) * 32u
                                      : 34816u + (unsigned)(ks - 16) * 32u;
            unsigned boff = (ks < 8) ? (unsigned)ks * 32u
                          : (ks < 16) ? 34816u + (unsigned)(ks - 8) * 32u
                                      : (unsigned)(ks - 16) * 32u;
            unsigned bf0[8], bf1[8];
            #pragma unroll
            for (int jp = 0; jp < 4; ++jp)
                ldm4(bf0[2 * jp], bf1[2 * jp], bf0[2 * jp + 1], bf1[2 * jp + 1],
                     bAddr + jp * 16 * 272 + boff);
            #pragma unroll
            for (int i = 0; i < 2; ++i) {
                unsigned a0, a1, a2, a3;
                ldm4(a0, a1, a2, a3, aAddr + aoff + i * 16 * 272);
                #pragma unroll
                for (int j = 0; j < 8; ++j)
                    mma16816(acc[i][j][0], acc[i][j][1], acc[i][j][2], acc[i][j][3],
                             a0, a1, a2, a3, bf0[j], bf1[j]);
            }
        }

        int b0idx = (int)(r0 / 62500);
        float s0 = 0.f, q0 = 0.f, s1 = 0.f, q1 = 0.f;
        #pragma unroll
        for (int i = 0; i < 2; ++i) {
            long ra = r0 + mw * 32 + i * 16 + g;
            long rb = ra + 8;
            #pragma unroll
            for (int j = 0; j < 8; ++j) {
                int c = nw * 64 + j * 8 + tg * 2;
                float bv0 = sbias[c], bv1 = sbias[c + 1];
                if (ra < NCOL) {
                    float v0 = acc[i][j][0] + bv0;
                    float v1 = acc[i][j][1] + bv1;
                    *(float2*)&g_buf1[ra * 128 + c] = make_float2(v0, v1);
                    float rs = v0 + v1, rq = v0 * v0 + v1 * v1;
                    if ((int)(ra / 62500) == b0idx) { s0 += rs; q0 += rq; }
                    else                            { s1 += rs; q1 += rq; }
                }
                if (rb < NCOL) {
                    float v2 = acc[i][j][2] + bv0;
                    float v3 = acc[i][j][3] + bv1;
                    *(float2*)&g_buf1[rb * 128 + c] = make_float2(v2, v3);
                    float rs = v2 + v3, rq = v2 * v2 + v3 * v3;
                    if ((int)(rb / 62500) == b0idx) { s0 += rs; q0 += rq; }
                    else                            { s1 += rs; q1 += rq; }
                }
            }
        }
        #pragma unroll
        for (int off = 16; off; off >>= 1) {
            s0 += __shfl_down_sync(0xffffffffu, s0, off);
            q0 += __shfl_down_sync(0xffffffffu, q0, off);
            s1 += __shfl_down_sync(0xffffffffu, s1, off);
            q1 += __shfl_down_sync(0xffffffffu, q1, off);
        }
        if (lane == 0) { red[w * 4 + 0] = s0; red[w * 4 + 1] = q0; red[w * 4 + 2] = s1; red[w * 4 + 3] = q1; }
        __syncthreads();
        if (tid == 0) {
            float ts0 = 0.f, tq0 = 0.f, ts1 = 0.f, tq1 = 0.f;
            #pragma unroll
            for (int j = 0; j < 8; ++j) {
                ts0 += red[j * 4 + 0]; tq0 += red[j * 4 + 1];
                ts1 += red[j * 4 + 2]; tq1 += red[j * 4 + 3];
            }
            atomicAdd(&g_stats[2 * b0idx],     (double)ts0);
            atomicAdd(&g_stats[2 * b0idx + 1], (double)tq0);
            if (b0idx < 3) {
                atomicAdd(&g_stats[2 * b0idx + 2], (double)ts1);
                atomicAdd(&g_stats[2 * b0idx + 3], (double)tq1);
            }
        }
        __syncthreads();   // protect Ghi/Glo + red before next tile
    }
}

// ---------------------------------------------------------------------------
__global__ void zero_stats() {
    if (threadIdx.x < 8) g_stats[threadIdx.x] = 0.0;
}

__global__ void finalize_stats() {
    int b = threadIdx.x;
    if (b < 4) {
        double mu  = g_stats[2 * b] / (double)PERB;
        double var = g_stats[2 * b + 1] / (double)PERB - mu * mu;
        g_mu[b]  = (float)mu;
        g_inv[b] = (float)(1.0 / sqrt(var + 1e-8));
    }
}

__global__ void trans_norm_intra(const float* __restrict__ gg, const float* __restrict__ gb,
                                 const float* __restrict__ x, float* __restrict__ out) {
    __shared__ float tile[32][33];
    int bn = blockIdx.y;
    int b = bn >> 7, n = bn & 127;
    int tk = blockIdx.x & 7, ts = blockIdx.x >> 3;
    int s = ts * 32 + threadIdx.y;
    int k = tk * 32 + threadIdx.x;
    if (s < 250 && k < 250)
        tile[threadIdx.y][threadIdx.x] =
            g_buf1[((long)(b * 250 + s)) * 32000 + n * 250 + k];
    __syncthreads();
    int k2 = tk * 32 + threadIdx.y;
    int s2 = ts * 32 + threadIdx.x;
    if (k2 < 250 && s2 < 250) {
        float mu = g_mu[b], inv = g_inv[b];
        long oi = (((long)(b * 128 + n)) * 250 + k2) * 250 + s2;
        float val = (tile[threadIdx.x][threadIdx.y] - mu) * inv * gg[n] + gb[n] + x[oi];
        out[oi] = val;
    }
}

__global__ void norm_final(const float* __restrict__ gg, const float* __restrict__ gb,
                           float* __restrict__ out) {
    int i = blockIdx.x * 256 + threadIdx.x;
    int s = i % 250;
    int t = i / 250;
    int k = t % 250; t /= 250;
    int n = t & 127;
    int b = t >> 7;
    float mu = g_mu[b], inv = g_inv[b];
    float v = g_buf1[((long)(b * 250 + k)) * 32000 + n * 250 + s];
    out[i] = (v - mu) * inv * gg[n] + gb[n] + out[i];
}

// ---------------------------------------------------------------------------
extern "C" void kernel_launch(void* const* d_in, const int* in_sizes, int n_in,
                              void* d_out, int out_size) {
    const float* x = (const float*)d_in[0];
    const float* ip[12];
    const float* pp[12];
    for (int j = 0; j < 12; ++j) ip[j] = (const float*)d_in[1 + j];
    for (int j = 0; j < 12; ++j) pp[j] = (const float*)d_in[13 + j];
    float* out = (float*)d_out;

    const int EB = TOT / 256;
    const int SMEM_OW = 190464;
    const int SMEM_LW = 139904;
    cudaFuncSetAttribute(gemm_ow_mma, cudaFuncAttributeMaxDynamicSharedMemorySize, SMEM_OW);
    cudaFuncSetAttribute(gemm_lw_mma, cudaFuncAttributeMaxDynamicSharedMemorySize, SMEM_LW);

    // ---- intra path ----
    pack_intra<<<dim3(64, 512), dim3(32, 32)>>>(x);
    kern_compute<<<NC, 256>>>(ip[0], ip[1], ip[2], ip[3], ip[4]);
    conv_gemm<<<dim3(16, 128), 256>>>(ip[5], (const float*)0, 0);
    conv_w_bf16<<<96, 256>>>(ip[6], ip[8]);
    gemm_ow_mma<<<NSM, 256, SMEM_OW>>>(ip[7]);
    zero_stats<<<1, 32>>>();
    gemm_lw_mma<<<NSM, 256, SMEM_LW>>>(ip[9]);
    finalize_stats<<<1, 32>>>();
    trans_norm_intra<<<dim3(64, 512), dim3(32, 32)>>>(ip[10], ip[11], x, out);

    // ---- inter path ----
    kern_compute<<<NC, 256>>>(pp[0], pp[1], pp[2], pp[3], pp[4]);
    conv_gemm<<<dim3(16, 128), 256>>>(pp[5], out, 1);
    conv_w_bf16<<<96, 256>>>(pp[6], pp[8]);
    gemm_ow_mma<<<NSM, 256, SMEM_OW>>>(pp[7]);
    zero_stats<<<1, 32>>>();
    gemm_lw_mma<<<NSM, 256, SMEM_LW>>>(pp[9]);
    finalize_stats<<<1, 32>>>();
    norm_final<<<EB, 256>>>(pp[10], pp[11], out);
}